// round 14
// baseline (speedup 1.0000x reference)
#include <cuda_runtime.h>
#include <cuda_bf16.h>
#include <cstdint>
#include <math.h>

// B=128, F=1024, W=32, H=64. Output = LSTM cell-state trajectory [B,W,H] fp32.
// Attention branch is dead code (softmax over a size-1 axis == 1).
//
// Gx = x^T-slices @ Wx via bf16x3 mma.sync GEMM (K expanded 1024 -> 3072:
// A chunks [hi,hi,lo] x B segs [hi,lo,hi]); then a latency-optimized LSTM
// (gate-interleaved, warp-shuffle cell update, 1 barrier/step, approx act).

__device__ __nv_bfloat16 g_A[4096u * 2048u];   // 16 MB: [m][0:1024)=hi, [1024:2048)=lo
__device__ __nv_bfloat16 g_B[256u * 3072u];    // 1.5 MB: [n][hi | lo | hi]
__device__ float         g_Gx[4096u * 256u];   // 4 MB gate pre-activations (no bias)

#define SWZ(o) ((o) ^ (((o) >> 3) & 0x70))

__device__ __forceinline__ uint32_t smem_u32(const void* p) {
    uint32_t a;
    asm("{ .reg .u64 t; cvta.to.shared.u64 t, %1; cvt.u32.u64 %0, t; }" : "=r"(a) : "l"(p));
    return a;
}
__device__ __forceinline__ void cp_async16(uint32_t dst, const void* src) {
    asm volatile("cp.async.cg.shared.global [%0], [%1], 16;" :: "r"(dst), "l"(src) : "memory");
}
__device__ __forceinline__ void cp_commit() { asm volatile("cp.async.commit_group;" ::: "memory"); }
template <int N> __device__ __forceinline__ void cp_wait() {
    asm volatile("cp.async.wait_group %0;" :: "n"(N) : "memory");
}
__device__ __forceinline__ void ldsm_x4(uint32_t* r, uint32_t addr) {
    asm volatile("ldmatrix.sync.aligned.m8n8.x4.shared.b16 {%0,%1,%2,%3}, [%4];"
                 : "=r"(r[0]), "=r"(r[1]), "=r"(r[2]), "=r"(r[3]) : "r"(addr));
}
__device__ __forceinline__ void mma_bf16(float* c, const uint32_t* a, uint32_t b0, uint32_t b1) {
    asm volatile(
        "mma.sync.aligned.m16n8k16.row.col.f32.bf16.bf16.f32 "
        "{%0,%1,%2,%3}, {%4,%5,%6,%7}, {%8,%9}, {%0,%1,%2,%3};"
        : "+f"(c[0]), "+f"(c[1]), "+f"(c[2]), "+f"(c[3])
        : "r"(a[0]), "r"(a[1]), "r"(a[2]), "r"(a[3]), "r"(b0), "r"(b1));
}
__device__ __forceinline__ unsigned long long pack2(float x, float y) {
    unsigned long long r; asm("mov.b64 %0, {%1, %2};" : "=l"(r) : "f"(x), "f"(y)); return r;
}
__device__ __forceinline__ void unpack2(unsigned long long v, float& x, float& y) {
    asm("mov.b64 {%0, %1}, %2;" : "=f"(x), "=f"(y) : "l"(v));
}
__device__ __forceinline__ void fma2(unsigned long long& d, unsigned long long a,
                                     unsigned long long b) {
    asm("fma.rn.f32x2 %0, %1, %2, %0;" : "+l"(d) : "l"(a), "l"(b));
}
__device__ __forceinline__ float ex2a(float x) {
    float r; asm("ex2.approx.f32 %0, %1;" : "=f"(r) : "f"(x)); return r;
}
__device__ __forceinline__ float rcpa(float x) {
    float r; asm("rcp.approx.f32 %0, %1;" : "=f"(r) : "f"(x)); return r;
}
__device__ __forceinline__ float siga(float x) {          // 1/(1+exp(-x))
    return rcpa(1.0f + ex2a(-1.4426950408889634f * x));
}
__device__ __forceinline__ float tanha(float x) {         // 2/(1+exp(-2x)) - 1
    return fmaf(2.0f, rcpa(1.0f + ex2a(-2.8853900817779268f * x)), -1.0f);
}

// ---------- prep: x[B,F,W] -> A[m=(b,t)][f] split hi/lo ----------------------
__global__ __launch_bounds__(256) void prep_x(const float* __restrict__ x,
                                              __nv_bfloat16* __restrict__ A) {
    __shared__ float tile[32][33];
    const int tid = threadIdx.x;
    const int b = blockIdx.y, f0 = blockIdx.x * 32;
    const float* xb = x + (size_t)b * 32768u + (size_t)f0 * 32u;
#pragma unroll
    for (int i = 0; i < 4; i++) {
        int idx = tid + i * 256, r = idx >> 5, t = idx & 31;
        tile[r][t] = xb[r * 32 + t];
    }
    __syncthreads();
#pragma unroll
    for (int i = 0; i < 2; i++) {
        int idx = tid + i * 256, t = idx >> 4, fp = idx & 15;
        float v0 = tile[2 * fp][t], v1 = tile[2 * fp + 1][t];
        __nv_bfloat16 h0 = __float2bfloat16(v0), h1 = __float2bfloat16(v1);
        __nv_bfloat16 l0 = __float2bfloat16(v0 - __bfloat162float(h0));
        __nv_bfloat16 l1 = __float2bfloat16(v1 - __bfloat162float(h1));
        size_t row = (size_t)(b * 32 + t) * 2048u + f0 + 2 * fp;
        __nv_bfloat162 hh; hh.x = h0; hh.y = h1;
        __nv_bfloat162 ll; ll.x = l0; ll.y = l1;
        *(__nv_bfloat162*)(A + row)         = hh;
        *(__nv_bfloat162*)(A + row + 1024u) = ll;
    }
}

// ---------- prep: Wx[F,4H] -> B[n][hi|lo|hi] --------------------------------
__global__ __launch_bounds__(256) void prep_w(const float* __restrict__ Wx,
                                              __nv_bfloat16* __restrict__ Bo) {
    __shared__ float tile[32][33];
    const int tid = threadIdx.x;
    const int n0 = blockIdx.x * 32, k0 = blockIdx.y * 32;
#pragma unroll
    for (int i = 0; i < 4; i++) {
        int idx = tid + i * 256, r = idx >> 5, c = idx & 31;
        tile[r][c] = Wx[(size_t)(k0 + r) * 256u + n0 + c];
    }
    __syncthreads();
#pragma unroll
    for (int i = 0; i < 2; i++) {
        int idx = tid + i * 256, t = idx >> 4, fp = idx & 15;
        float v0 = tile[2 * fp][t], v1 = tile[2 * fp + 1][t];
        __nv_bfloat16 h0 = __float2bfloat16(v0), h1 = __float2bfloat16(v1);
        __nv_bfloat16 l0 = __float2bfloat16(v0 - __bfloat162float(h0));
        __nv_bfloat16 l1 = __float2bfloat16(v1 - __bfloat162float(h1));
        size_t row = (size_t)(n0 + t) * 3072u + k0 + 2 * fp;
        __nv_bfloat162 hh; hh.x = h0; hh.y = h1;
        __nv_bfloat162 ll; ll.x = l0; ll.y = l1;
        *(__nv_bfloat162*)(Bo + row)         = hh;
        *(__nv_bfloat162*)(Bo + row + 1024u) = ll;
        *(__nv_bfloat162*)(Bo + row + 2048u) = hh;
    }
}

// ---------- bf16x3 mma.sync GEMM: Gx[m][n], M=4096 N=256 K'=3072 ------------
__global__ __launch_bounds__(256) void gemm_kernel(const __nv_bfloat16* __restrict__ A,
                                                   const __nv_bfloat16* __restrict__ Bg,
                                                   float* __restrict__ Gx) {
    __shared__ __align__(1024) char sm[49152];   // A:2x16K, B:2x8K
    const int tid = threadIdx.x, lane = tid & 31, wid = tid >> 5;
    const int wm = wid & 3, wn = wid >> 2;
    const int n0 = blockIdx.x * 64, m0 = blockIdx.y * 128;
    const uint32_t smb = smem_u32(sm);
    const uint32_t Aoff[2] = {0u, 24576u};
    const uint32_t Boff[2] = {16384u, 40960u};

    float acc[2][4][4];
#pragma unroll
    for (int i = 0; i < 2; i++)
#pragma unroll
        for (int j = 0; j < 4; j++)
#pragma unroll
            for (int q = 0; q < 4; q++) acc[i][j][q] = 0.0f;

    const uint32_t xm = (uint32_t)((lane & 7) << 4);
    uint32_t oA[2], oB[2];
#pragma unroll
    for (int i = 0; i < 2; i++) {
        int rowA = wm * 32 + i * 16 + (lane & 15);
        oA[i] = (uint32_t)(rowA * 128 + (lane >> 4) * 16);
    }
#pragma unroll
    for (int jp = 0; jp < 2; jp++) {
        int rowB = wn * 32 + jp * 16 + ((lane & 16) ? 8 : 0) + (lane & 7);
        oB[jp] = (uint32_t)(rowB * 128 + ((lane & 8) ? 16 : 0));
    }

    auto load_chunk = [&](int c, int buf) {
        const int kA = (c < 16) ? c * 64 : (c < 32) ? (c - 16) * 64 : 1024 + (c - 32) * 64;
        const int kB = c * 64;
#pragma unroll
        for (int i = 0; i < 4; i++) {
            int cid = tid + i * 256, r = cid >> 3, q = cid & 7;
            const void* src = A + (size_t)(m0 + r) * 2048u + kA + q * 8;
            cp_async16(smb + Aoff[buf] + SWZ((uint32_t)(r * 128 + q * 16)), src);
        }
#pragma unroll
        for (int i = 0; i < 2; i++) {
            int cid = tid + i * 256, r = cid >> 3, q = cid & 7;
            const void* src = Bg + (size_t)(n0 + r) * 3072u + kB + q * 8;
            cp_async16(smb + Boff[buf] + SWZ((uint32_t)(r * 128 + q * 16)), src);
        }
        cp_commit();
    };

    load_chunk(0, 0);
    for (int c = 0; c < 48; c++) {
        const int buf = c & 1;
        if (c < 47) { load_chunk(c + 1, buf ^ 1); cp_wait<1>(); }
        else        { cp_wait<0>(); }
        __syncthreads();
        const uint32_t AS = smb + Aoff[buf], BS = smb + Boff[buf];
#pragma unroll
        for (int k16 = 0; k16 < 4; k16++) {
            const uint32_t bk = (uint32_t)(k16 * 32);
            uint32_t af[2][4], bf[2][4];
#pragma unroll
            for (int i = 0; i < 2; i++) ldsm_x4(af[i], AS + ((oA[i] + bk) ^ xm));
#pragma unroll
            for (int jp = 0; jp < 2; jp++) ldsm_x4(bf[jp], BS + ((oB[jp] + bk) ^ xm));
#pragma unroll
            for (int i = 0; i < 2; i++)
#pragma unroll
                for (int j = 0; j < 4; j++)
                    mma_bf16(acc[i][j], af[i], bf[j >> 1][(j & 1) * 2], bf[j >> 1][(j & 1) * 2 + 1]);
        }
        __syncthreads();
    }

#pragma unroll
    for (int i = 0; i < 2; i++) {
        int mg = m0 + wm * 32 + i * 16 + (lane >> 2);
#pragma unroll
        for (int j = 0; j < 4; j++) {
            int ng = n0 + wn * 32 + j * 8 + 2 * (lane & 3);
            float2 lo; lo.x = acc[i][j][0]; lo.y = acc[i][j][1];
            float2 hi; hi.x = acc[i][j][2]; hi.y = acc[i][j][3];
            *(float2*)(Gx + (size_t)mg * 256u + ng)        = lo;
            *(float2*)(Gx + (size_t)(mg + 8) * 256u + ng)  = hi;
        }
    }
}

// ---------- LSTM recurrence: gate-interleaved, 1 barrier/step ---------------
// Thread n: gate g=n&3 of unit u=n>>2 (gate column col=g*64+u). All 4 gates of
// a unit sit in adjacent lanes -> cell update via 4 shfl, redundant per-lane c.
// h double-buffered in SMEM -> single __syncthreads per step.
__global__ __launch_bounds__(256) void lstm_kernel(const float* __restrict__ Wh,
                                                   const float* __restrict__ bias,
                                                   const float* __restrict__ Gx,
                                                   float* __restrict__ out) {
    __shared__ float gsum[8192];                 // 32 steps x 256 (unpermuted)
    __shared__ __align__(16) float hsbuf[2][64];
    const int b = blockIdx.x, n = threadIdx.x;
    const int g = n & 3, u = n >> 2;
    const int col = g * 64 + u;
    const int bl = (n & 31) & ~3;                // shuffle base lane

    unsigned long long w2[32];
#pragma unroll
    for (int j = 0; j < 32; j++)
        w2[j] = pack2(Wh[(2 * j) * 256 + col], Wh[(2 * j + 1) * 256 + col]);
    const float bcol = bias[col];

    const float4* gp = (const float4*)(Gx + (size_t)b * 8192u);
#pragma unroll
    for (int i = 0; i < 8; i++) {
        int idx = n + i * 256;
        *(float4*)&gsum[idx * 4] = gp[idx];
    }
    if (n < 64) hsbuf[0][n] = 0.0f;
    float cst = 0.0f;
    __syncthreads();

    const float* hr = hsbuf[0];
    float* hw = hsbuf[1];
    for (int t = 0; t < 32; t++) {
        unsigned long long s0 = 0, s1 = 0, s2 = 0, s3 = 0;
        const ulonglong2* hv = (const ulonglong2*)hr;
#pragma unroll
        for (int j = 0; j < 16; j++) {
            ulonglong2 h2 = hv[j];
            if (j & 1) { fma2(s2, h2.x, w2[2 * j]); fma2(s3, h2.y, w2[2 * j + 1]); }
            else       { fma2(s0, h2.x, w2[2 * j]); fma2(s1, h2.y, w2[2 * j + 1]); }
        }
        float x0, x1, y0, y1, z0, z1, q0, q1;
        unpack2(s0, x0, x1); unpack2(s1, y0, y1);
        unpack2(s2, z0, z1); unpack2(s3, q0, q1);
        float acc = gsum[t * 256 + col] + bcol +
                    ((x0 + x1) + (y0 + y1)) + ((z0 + z1) + (q0 + q1));
        float v = (g == 2) ? tanha(acc) : siga(acc);

        float xi = __shfl_sync(0xffffffffu, v, bl + 0);
        float xf = __shfl_sync(0xffffffffu, v, bl + 1);
        float xg = __shfl_sync(0xffffffffu, v, bl + 2);
        float xo = __shfl_sync(0xffffffffu, v, bl + 3);

        cst = fmaf(xf, cst, xi * xg);
        float h = xo * tanha(cst);
        if (g == 0) {
            hw[u] = h;
            out[(size_t)b * 2048u + (size_t)t * 64u + u] = cst;
        }
        const float* tmp = hr; hr = hw; hw = (float*)tmp;
        __syncthreads();
    }
}

extern "C" void kernel_launch(void* const* d_in, const int* in_sizes, int n_in,
                              void* d_out, int out_size) {
    const float* x      = (const float*)d_in[0];   // [128,1024,32]
    const float* Wx     = (const float*)d_in[6];   // [1024,256]
    const float* Wh     = (const float*)d_in[7];   // [64,256]
    const float* b_lstm = (const float*)d_in[8];   // [256]
    float* out = (float*)d_out;                    // [128,32,64]

    __nv_bfloat16 *A, *Bg;
    float* Gx;
    cudaGetSymbolAddress((void**)&A, g_A);
    cudaGetSymbolAddress((void**)&Bg, g_B);
    cudaGetSymbolAddress((void**)&Gx, g_Gx);

    prep_x<<<dim3(32, 128), 256>>>(x, A);
    prep_w<<<dim3(8, 32), 256>>>(Wx, Bg);
    gemm_kernel<<<dim3(4, 32), 256>>>(A, Bg, Gx);
    lstm_kernel<<<128, 256>>>(Wh, b_lstm, Gx, out);
}

// round 16
// speedup vs baseline: 1.0024x; 1.0024x over previous
#include <cuda_runtime.h>
#include <cuda_bf16.h>
#include <cstdint>
#include <math.h>

// B=128, F=1024, W=32, H=64. Output = LSTM cell-state trajectory [B,W,H] fp32.
// Attention branch is dead code (softmax over a size-1 axis == 1).
//
// Gx = x^T-slices @ Wx via bf16x3 mma.sync GEMM (K expanded 1024 -> 3072:
// A chunks [hi,hi,lo] x B segs [hi,lo,hi]); then a latency-optimized LSTM.

__device__ __nv_bfloat16 g_A[4096u * 2048u];   // 16 MB: [m][0:1024)=hi, [1024:2048)=lo
__device__ __nv_bfloat16 g_B[256u * 3072u];    // 1.5 MB: [n][hi | lo | hi]
__device__ float         g_Gx[4096u * 256u];   // 4 MB gate pre-activations (no bias)

#define SWZ(o) ((o) ^ (((o) >> 3) & 0x70))

__device__ __forceinline__ uint32_t smem_u32(const void* p) {
    uint32_t a;
    asm("{ .reg .u64 t; cvta.to.shared.u64 t, %1; cvt.u32.u64 %0, t; }" : "=r"(a) : "l"(p));
    return a;
}
__device__ __forceinline__ void cp_async16(uint32_t dst, const void* src) {
    asm volatile("cp.async.cg.shared.global [%0], [%1], 16;" :: "r"(dst), "l"(src) : "memory");
}
__device__ __forceinline__ void cp_commit() { asm volatile("cp.async.commit_group;" ::: "memory"); }
template <int N> __device__ __forceinline__ void cp_wait() {
    asm volatile("cp.async.wait_group %0;" :: "n"(N) : "memory");
}
__device__ __forceinline__ void ldsm_x4(uint32_t* r, uint32_t addr) {
    asm volatile("ldmatrix.sync.aligned.m8n8.x4.shared.b16 {%0,%1,%2,%3}, [%4];"
                 : "=r"(r[0]), "=r"(r[1]), "=r"(r[2]), "=r"(r[3]) : "r"(addr));
}
__device__ __forceinline__ void mma_bf16(float* c, const uint32_t* a, uint32_t b0, uint32_t b1) {
    asm volatile(
        "mma.sync.aligned.m16n8k16.row.col.f32.bf16.bf16.f32 "
        "{%0,%1,%2,%3}, {%4,%5,%6,%7}, {%8,%9}, {%0,%1,%2,%3};"
        : "+f"(c[0]), "+f"(c[1]), "+f"(c[2]), "+f"(c[3])
        : "r"(a[0]), "r"(a[1]), "r"(a[2]), "r"(a[3]), "r"(b0), "r"(b1));
}
__device__ __forceinline__ unsigned long long pack2(float x, float y) {
    unsigned long long r; asm("mov.b64 %0, {%1, %2};" : "=l"(r) : "f"(x), "f"(y)); return r;
}
__device__ __forceinline__ void unpack2(unsigned long long v, float& x, float& y) {
    asm("mov.b64 {%0, %1}, %2;" : "=f"(x), "=f"(y) : "l"(v));
}
__device__ __forceinline__ void fma2(unsigned long long& d, unsigned long long a,
                                     unsigned long long b) {
    asm("fma.rn.f32x2 %0, %1, %2, %0;" : "+l"(d) : "l"(a), "l"(b));
}
__device__ __forceinline__ float ex2a(float x) {
    float r; asm("ex2.approx.f32 %0, %1;" : "=f"(r) : "f"(x)); return r;
}
__device__ __forceinline__ float rcpa(float x) {
    float r; asm("rcp.approx.f32 %0, %1;" : "=f"(r) : "f"(x)); return r;
}
__device__ __forceinline__ float siga(float x) {          // 1/(1+exp(-x))
    return rcpa(1.0f + ex2a(-1.4426950408889634f * x));
}
__device__ __forceinline__ float tanha(float x) {         // 2/(1+exp(-2x)) - 1
    return fmaf(2.0f, rcpa(1.0f + ex2a(-2.8853900817779268f * x)), -1.0f);
}

// ---------- merged prep: x -> A (hi/lo), Wx -> B (hi|lo|hi) -----------------
__global__ __launch_bounds__(256) void prep_kernel(const float* __restrict__ x,
                                                   const float* __restrict__ Wx,
                                                   __nv_bfloat16* __restrict__ A,
                                                   __nv_bfloat16* __restrict__ Bo) {
    __shared__ float tile[32][33];
    const int tid = threadIdx.x;
    const int bid = blockIdx.x;
    if (bid < 4096) {
        // x[B,F,W] -> A[m=(b,t)][f] split hi/lo
        const int b = bid >> 5, f0 = (bid & 31) * 32;
        const float* xb = x + (size_t)b * 32768u + (size_t)f0 * 32u;
#pragma unroll
        for (int i = 0; i < 4; i++) {
            int idx = tid + i * 256, r = idx >> 5, t = idx & 31;
            tile[r][t] = xb[r * 32 + t];
        }
        __syncthreads();
#pragma unroll
        for (int i = 0; i < 2; i++) {
            int idx = tid + i * 256, t = idx >> 4, fp = idx & 15;
            float v0 = tile[2 * fp][t], v1 = tile[2 * fp + 1][t];
            __nv_bfloat16 h0 = __float2bfloat16(v0), h1 = __float2bfloat16(v1);
            __nv_bfloat16 l0 = __float2bfloat16(v0 - __bfloat162float(h0));
            __nv_bfloat16 l1 = __float2bfloat16(v1 - __bfloat162float(h1));
            size_t row = (size_t)(b * 32 + t) * 2048u + f0 + 2 * fp;
            __nv_bfloat162 hh; hh.x = h0; hh.y = h1;
            __nv_bfloat162 ll; ll.x = l0; ll.y = l1;
            *(__nv_bfloat162*)(A + row)         = hh;
            *(__nv_bfloat162*)(A + row + 1024u) = ll;
        }
    } else {
        // Wx[F,4H] -> B[n][hi|lo|hi]
        const int id = bid - 4096;
        const int n0 = (id & 7) * 32, k0 = (id >> 3) * 32;
#pragma unroll
        for (int i = 0; i < 4; i++) {
            int idx = tid + i * 256, r = idx >> 5, c = idx & 31;
            tile[r][c] = Wx[(size_t)(k0 + r) * 256u + n0 + c];
        }
        __syncthreads();
#pragma unroll
        for (int i = 0; i < 2; i++) {
            int idx = tid + i * 256, t = idx >> 4, fp = idx & 15;
            float v0 = tile[2 * fp][t], v1 = tile[2 * fp + 1][t];
            __nv_bfloat16 h0 = __float2bfloat16(v0), h1 = __float2bfloat16(v1);
            __nv_bfloat16 l0 = __float2bfloat16(v0 - __bfloat162float(h0));
            __nv_bfloat16 l1 = __float2bfloat16(v1 - __bfloat162float(h1));
            size_t row = (size_t)(n0 + t) * 3072u + k0 + 2 * fp;
            __nv_bfloat162 hh; hh.x = h0; hh.y = h1;
            __nv_bfloat162 ll; ll.x = l0; ll.y = l1;
            *(__nv_bfloat162*)(Bo + row)         = hh;
            *(__nv_bfloat162*)(Bo + row + 1024u) = ll;
            *(__nv_bfloat162*)(Bo + row + 2048u) = hh;
        }
    }
}

// ---------- bf16x3 mma.sync GEMM: Gx[m][n], M=4096 N=256 K'=3072 ------------
__global__ __launch_bounds__(256) void gemm_kernel(const __nv_bfloat16* __restrict__ A,
                                                   const __nv_bfloat16* __restrict__ Bg,
                                                   float* __restrict__ Gx) {
    __shared__ __align__(1024) char sm[49152];   // A:2x16K, B:2x8K
    const int tid = threadIdx.x, lane = tid & 31, wid = tid >> 5;
    const int wm = wid & 3, wn = wid >> 2;
    const int n0 = blockIdx.x * 64, m0 = blockIdx.y * 128;
    const uint32_t smb = smem_u32(sm);
    const uint32_t Aoff[2] = {0u, 24576u};
    const uint32_t Boff[2] = {16384u, 40960u};

    float acc[2][4][4];
#pragma unroll
    for (int i = 0; i < 2; i++)
#pragma unroll
        for (int j = 0; j < 4; j++)
#pragma unroll
            for (int q = 0; q < 4; q++) acc[i][j][q] = 0.0f;

    const uint32_t xm = (uint32_t)((lane & 7) << 4);
    uint32_t oA[2], oB[2];
#pragma unroll
    for (int i = 0; i < 2; i++) {
        int rowA = wm * 32 + i * 16 + (lane & 15);
        oA[i] = (uint32_t)(rowA * 128 + (lane >> 4) * 16);
    }
#pragma unroll
    for (int jp = 0; jp < 2; jp++) {
        int rowB = wn * 32 + jp * 16 + ((lane & 16) ? 8 : 0) + (lane & 7);
        oB[jp] = (uint32_t)(rowB * 128 + ((lane & 8) ? 16 : 0));
    }

    auto load_chunk = [&](int c, int buf) {
        const int kA = (c < 16) ? c * 64 : (c < 32) ? (c - 16) * 64 : 1024 + (c - 32) * 64;
        const int kB = c * 64;
#pragma unroll
        for (int i = 0; i < 4; i++) {
            int cid = tid + i * 256, r = cid >> 3, q = cid & 7;
            const void* src = A + (size_t)(m0 + r) * 2048u + kA + q * 8;
            cp_async16(smb + Aoff[buf] + SWZ((uint32_t)(r * 128 + q * 16)), src);
        }
#pragma unroll
        for (int i = 0; i < 2; i++) {
            int cid = tid + i * 256, r = cid >> 3, q = cid & 7;
            const void* src = Bg + (size_t)(n0 + r) * 3072u + kB + q * 8;
            cp_async16(smb + Boff[buf] + SWZ((uint32_t)(r * 128 + q * 16)), src);
        }
        cp_commit();
    };

    load_chunk(0, 0);
    for (int c = 0; c < 48; c++) {
        const int buf = c & 1;
        if (c < 47) { load_chunk(c + 1, buf ^ 1); cp_wait<1>(); }
        else        { cp_wait<0>(); }
        __syncthreads();
        const uint32_t AS = smb + Aoff[buf], BS = smb + Boff[buf];
#pragma unroll
        for (int k16 = 0; k16 < 4; k16++) {
            const uint32_t bk = (uint32_t)(k16 * 32);
            uint32_t af[2][4], bf[2][4];
#pragma unroll
            for (int i = 0; i < 2; i++) ldsm_x4(af[i], AS + ((oA[i] + bk) ^ xm));
#pragma unroll
            for (int jp = 0; jp < 2; jp++) ldsm_x4(bf[jp], BS + ((oB[jp] + bk) ^ xm));
#pragma unroll
            for (int i = 0; i < 2; i++)
#pragma unroll
                for (int j = 0; j < 4; j++)
                    mma_bf16(acc[i][j], af[i], bf[j >> 1][(j & 1) * 2], bf[j >> 1][(j & 1) * 2 + 1]);
        }
        __syncthreads();
    }

#pragma unroll
    for (int i = 0; i < 2; i++) {
        int mg = m0 + wm * 32 + i * 16 + (lane >> 2);
#pragma unroll
        for (int j = 0; j < 4; j++) {
            int ng = n0 + wn * 32 + j * 8 + 2 * (lane & 3);
            float2 lo; lo.x = acc[i][j][0]; lo.y = acc[i][j][1];
            float2 hi; hi.x = acc[i][j][2]; hi.y = acc[i][j][3];
            *(float2*)(Gx + (size_t)mg * 256u + ng)        = lo;
            *(float2*)(Gx + (size_t)(mg + 8) * 256u + ng)  = hi;
        }
    }
}

// ---------- LSTM recurrence ----------------------------------------------
// Thread n: gate g=n&3 of unit u=n>>2 (col=g*64+u). Cell update via 4 shfl.
// Static ping-pong h buffers, bias folded at preload, gsum[t+1] prefetched
// across the barrier, tanh(c)/h/stores on g==0 lanes only.
__global__ __launch_bounds__(256) void lstm_kernel(const float* __restrict__ Wh,
                                                   const float* __restrict__ bias,
                                                   const float* __restrict__ Gx,
                                                   float* __restrict__ out) {
    __shared__ float gsum[8192];                 // 32 steps x 256 (bias folded)
    __shared__ __align__(16) float hs0[64];
    __shared__ __align__(16) float hs1[64];
    const int b = blockIdx.x, n = threadIdx.x;
    const int g = n & 3, u = n >> 2;
    const int col = g * 64 + u;
    const int bl = (n & 31) & ~3;                // shuffle base lane

    unsigned long long w2[32];
#pragma unroll
    for (int j = 0; j < 32; j++)
        w2[j] = pack2(Wh[(2 * j) * 256 + col], Wh[(2 * j + 1) * 256 + col]);

    const float4* gp = (const float4*)(Gx + (size_t)b * 8192u);
#pragma unroll
    for (int i = 0; i < 8; i++) {
        int idx = n + i * 256;
        float4 a = gp[idx];
        float4 bv = *(const float4*)(bias + (idx & 63) * 4);
        a.x += bv.x; a.y += bv.y; a.z += bv.z; a.w += bv.w;
        *(float4*)&gsum[idx * 4] = a;
    }
    if (n < 64) hs0[n] = 0.0f;
    float cst = 0.0f;
    __syncthreads();

    float gx_cur = gsum[col];                    // t = 0 (prefetched)
    float* outb = out + (size_t)b * 2048u + u;

    auto step = [&](const float* hr, float* hw, int t) {
        unsigned long long s0 = 0, s1 = 0, s2 = 0, s3 = 0;
        const ulonglong2* hv = (const ulonglong2*)hr;
#pragma unroll
        for (int j = 0; j < 16; j++) {
            ulonglong2 h2 = hv[j];
            if (j & 1) { fma2(s2, h2.x, w2[2 * j]); fma2(s3, h2.y, w2[2 * j + 1]); }
            else       { fma2(s0, h2.x, w2[2 * j]); fma2(s1, h2.y, w2[2 * j + 1]); }
        }
        float x0, x1, y0, y1, z0, z1, q0, q1;
        unpack2(s0, x0, x1); unpack2(s1, y0, y1);
        unpack2(s2, z0, z1); unpack2(s3, q0, q1);
        float acc = gx_cur + ((x0 + x1) + (y0 + y1)) + ((z0 + z1) + (q0 + q1));
        gx_cur = gsum[((t + 1) & 31) * 256 + col];   // prefetch next step's Gx
        float v = (g == 2) ? tanha(acc) : siga(acc);

        float xi = __shfl_sync(0xffffffffu, v, bl + 0);
        float xf = __shfl_sync(0xffffffffu, v, bl + 1);
        float xg = __shfl_sync(0xffffffffu, v, bl + 2);
        float xo = __shfl_sync(0xffffffffu, v, bl + 3);

        cst = fmaf(xf, cst, xi * xg);
        if (g == 0) {
            hw[u] = xo * tanha(cst);
            outb[(size_t)t * 64u] = cst;
        }
        __syncthreads();
    };

    for (int t = 0; t < 32; t += 2) {
        step(hs0, hs1, t);
        step(hs1, hs0, t + 1);
    }
}

extern "C" void kernel_launch(void* const* d_in, const int* in_sizes, int n_in,
                              void* d_out, int out_size) {
    const float* x      = (const float*)d_in[0];   // [128,1024,32]
    const float* Wx     = (const float*)d_in[6];   // [1024,256]
    const float* Wh     = (const float*)d_in[7];   // [64,256]
    const float* b_lstm = (const float*)d_in[8];   // [256]
    float* out = (float*)d_out;                    // [128,32,64]

    __nv_bfloat16 *A, *Bg;
    float* Gx;
    cudaGetSymbolAddress((void**)&A, g_A);
    cudaGetSymbolAddress((void**)&Bg, g_B);
    cudaGetSymbolAddress((void**)&Gx, g_Gx);

    prep_kernel<<<4352, 256>>>(x, Wx, A, Bg);
    gemm_kernel<<<dim3(4, 32), 256>>>(A, Bg, Gx);
    lstm_kernel<<<128, 256>>>(Wh, b_lstm, Gx, out);
}